// round 17
// baseline (speedup 1.0000x reference)
#include <cuda_runtime.h>

#define B   64
#define T   100
#define NI  700
#define NH  512
#define NO  20
#define TAUc 0.6f
#define KAPc 0.6f
#define THRc 0.6f
#define LRc  0.05f

// ---------------- persistent device scratch ----------------
__device__ float g_XP  [T*B*NH];   // x @ W1^T, rows m = t*B+b
__device__ float g_TIN [T*B*NI];
__device__ float g_TREC[T*B*NH];
__device__ float g_HT  [T*B*NH];
__device__ float g_Z   [T*B*NH];
__device__ float g_EF  [T*B*NO];
__device__ float g_A   [T*B*NH];

// gradient split-K partials: gf 7 parts, gr 8 parts, go 8 parts
#define GF_MN (NH*NI)
#define GR_MN (NH*NH)
#define GO_MN (NO*NH)
#define GFP_OFF 0
#define GRP_OFF (7*GF_MN)
#define GOP_OFF (GRP_OFF + 8*GR_MN)
__device__ float g_gp[GOP_OFF + 8*GO_MN];

#define PROD_SMEM (2 * 16 * 129 * 4)       // 16512 B (big-tile max)
#define FWD_SMEM  ((NO*NH + NH + T*NO + NH + 64 + 16) * 4)   // 53376 B

// ---------------- f32x2 packed helpers (SASS FFMA2/FADD2) ----------------
__device__ __forceinline__ unsigned long long pk2(float x, float y) {
    unsigned long long r;
    asm("mov.b64 %0, {%1, %2};" : "=l"(r) : "f"(x), "f"(y));
    return r;
}
__device__ __forceinline__ void upk2(float& x, float& y, unsigned long long v) {
    asm("mov.b64 {%0, %1}, %2;" : "=f"(x), "=f"(y) : "l"(v));
}
__device__ __forceinline__ void ffma2(unsigned long long& d, unsigned long long a,
                                      unsigned long long b) {
    asm("fma.rn.f32x2 %0, %1, %2, %0;" : "+l"(d) : "l"(a), "l"(b));
}
__device__ __forceinline__ void fadd2(unsigned long long& d, unsigned long long a) {
    asm("add.rn.f32x2 %0, %0, %1;" : "+l"(d) : "l"(a));
}

// ============================================================================
// k_prod: gemmX small [0,64) | gemmX big [64,232) | tin [232,407)
// gemmX bodies verbatim (PRECISION-CRITICAL — bitwise-identical XP).
// ============================================================================
__global__ __launch_bounds__(256, 2) void k_prod(const float* __restrict__ x,
                                                 const float* __restrict__ w1) {
    extern __shared__ char smraw[];
    int bid = blockIdx.x;
    int tid = threadIdx.x;

    if (bid < 64) {
        // ---------------- gemmX SMALL tile: 64 x 128, m-tiles 0..7 ----------------
        float (*As)[64]  = (float(*)[64])smraw;
        float (*Bs)[128] = (float(*)[128])(smraw + 16 * 64 * 4);
        int i = bid;
        int p = i >> 3;
        int sub = (i >> 2) & 1;
        int m0 = p * 128 + sub * 64;
        int n0 = (i & 3) * 128;
        int tx = tid & 15, ty = tid >> 4;
        unsigned long long acc2[4][4];
#pragma unroll
        for (int ii = 0; ii < 4; ii++)
#pragma unroll
            for (int jj = 0; jj < 4; jj++) acc2[ii][jj] = 0ull;

        for (int k0 = 0; k0 < NI; k0 += 16) {
            {
                int mm = tid & 63, kq = tid >> 6;
                int kg = k0 + kq * 4;
                int m = m0 + mm, t = m >> 6, b = m & 63;
                const float* xp = &x[((size_t)b * T + t) * NI + kg];
                float4 v;
                if (kg + 3 < NI) v = *(const float4*)xp;
                else {
                    v.x = (kg + 0 < NI) ? xp[0] : 0.f;
                    v.y = (kg + 1 < NI) ? xp[1] : 0.f;
                    v.z = (kg + 2 < NI) ? xp[2] : 0.f;
                    v.w = (kg + 3 < NI) ? xp[3] : 0.f;
                }
                As[kq * 4 + 0][mm] = v.x; As[kq * 4 + 1][mm] = v.y;
                As[kq * 4 + 2][mm] = v.z; As[kq * 4 + 3][mm] = v.w;
            }
            {
                int nn = tid & 127, kq = tid >> 7;
                int kg = k0 + kq * 8;
                const float* wp = &w1[(size_t)(n0 + nn) * NI + kg];
#pragma unroll
                for (int u = 0; u < 8; u++)
                    Bs[kq * 8 + u][nn] = (kg + u < NI) ? wp[u] : 0.f;
            }
            __syncthreads();
#pragma unroll
            for (int k = 0; k < 16; k++) {
                float a[4], bb[8];
                *(float4*)&a[0]  = *(float4*)&As[k][ty * 4];
                *(float4*)&bb[0] = *(float4*)&Bs[k][tx * 8];
                *(float4*)&bb[4] = *(float4*)&Bs[k][tx * 8 + 4];
                unsigned long long b2[4];
#pragma unroll
                for (int jj = 0; jj < 4; jj++) b2[jj] = pk2(bb[2 * jj], bb[2 * jj + 1]);
#pragma unroll
                for (int ii = 0; ii < 4; ii++) {
                    unsigned long long a2 = pk2(a[ii], a[ii]);
#pragma unroll
                    for (int jj = 0; jj < 4; jj++) ffma2(acc2[ii][jj], a2, b2[jj]);
                }
            }
            __syncthreads();
        }
#pragma unroll
        for (int ii = 0; ii < 4; ii++) {
            int m = m0 + ty * 4 + ii;
            float av[8];
#pragma unroll
            for (int jj = 0; jj < 4; jj++) upk2(av[2 * jj], av[2 * jj + 1], acc2[ii][jj]);
#pragma unroll
            for (int j = 0; j < 8; j++)
                g_XP[(size_t)m * NH + n0 + tx * 8 + j] = av[j];
        }
        return;
    }

    if (bid < 232) {
        // ---------------- gemmX 128 x 128 tile: m-tiles 8..49 ----------------
        float (*As)[129] = (float(*)[129])smraw;
        float (*Bs)[129] = (float(*)[129])(smraw + 16 * 129 * 4);
        int i = bid - 64;
        int p = 8 + (i >> 2);
        int m0 = p * 128, n0 = (i & 3) * 128;
        int tx = tid & 15, ty = tid >> 4;
        unsigned long long acc2[8][4];
#pragma unroll
        for (int ii = 0; ii < 8; ii++)
#pragma unroll
            for (int jj = 0; jj < 4; jj++) acc2[ii][jj] = 0ull;
        float4 va[2], vb[2];

        auto ldtile = [&](int k0) {
#pragma unroll
            for (int rep = 0; rep < 2; rep++) {
                int f = tid + rep * 256;
                int mm = f >> 2, kq = f & 3;
                int kg = k0 + kq * 4;
                {
                    int m = m0 + mm, t = m >> 6, b = m & 63;
                    const float* xp = &x[((size_t)b * T + t) * NI + kg];
                    float4 v;
                    if (kg + 3 < NI) v = *(const float4*)xp;
                    else {
                        v.x = (kg + 0 < NI) ? xp[0] : 0.f;
                        v.y = (kg + 1 < NI) ? xp[1] : 0.f;
                        v.z = (kg + 2 < NI) ? xp[2] : 0.f;
                        v.w = (kg + 3 < NI) ? xp[3] : 0.f;
                    }
                    va[rep] = v;
                }
                {
                    int n = n0 + mm;
                    const float* wp = &w1[(size_t)n * NI + kg];
                    float4 v;
                    if (kg + 3 < NI) v = *(const float4*)wp;
                    else {
                        v.x = (kg + 0 < NI) ? wp[0] : 0.f;
                        v.y = (kg + 1 < NI) ? wp[1] : 0.f;
                        v.z = (kg + 2 < NI) ? wp[2] : 0.f;
                        v.w = (kg + 3 < NI) ? wp[3] : 0.f;
                    }
                    vb[rep] = v;
                }
            }
        };
        auto sttile = [&]() {
#pragma unroll
            for (int rep = 0; rep < 2; rep++) {
                int f = tid + rep * 256;
                int mm = f >> 2, kq = f & 3;
                As[kq * 4 + 0][mm] = va[rep].x; As[kq * 4 + 1][mm] = va[rep].y;
                As[kq * 4 + 2][mm] = va[rep].z; As[kq * 4 + 3][mm] = va[rep].w;
                Bs[kq * 4 + 0][mm] = vb[rep].x; Bs[kq * 4 + 1][mm] = vb[rep].y;
                Bs[kq * 4 + 2][mm] = vb[rep].z; Bs[kq * 4 + 3][mm] = vb[rep].w;
            }
        };

        ldtile(0);
        for (int k0 = 0; k0 < NI; k0 += 16) {
            sttile();
            __syncthreads();
            if (k0 + 16 < NI) ldtile(k0 + 16);
#pragma unroll
            for (int k = 0; k < 16; k++) {
                float a[8], bb[8];
#pragma unroll
                for (int ii = 0; ii < 4; ii++) {
                    a[ii]      = As[k][ty * 4 + ii];
                    a[4 + ii]  = As[k][64 + ty * 4 + ii];
                    bb[ii]     = Bs[k][tx * 4 + ii];
                    bb[4 + ii] = Bs[k][64 + tx * 4 + ii];
                }
                unsigned long long b2[4];
#pragma unroll
                for (int jj = 0; jj < 4; jj++) b2[jj] = pk2(bb[2 * jj], bb[2 * jj + 1]);
#pragma unroll
                for (int ii = 0; ii < 8; ii++) {
                    unsigned long long a2 = pk2(a[ii], a[ii]);
#pragma unroll
                    for (int jj = 0; jj < 4; jj++) ffma2(acc2[ii][jj], a2, b2[jj]);
                }
            }
            __syncthreads();
        }
#pragma unroll
        for (int ii = 0; ii < 8; ii++) {
            int m = m0 + ((ii < 4) ? ty * 4 + ii : 64 + ty * 4 + (ii - 4));
            float av[8];
#pragma unroll
            for (int jj = 0; jj < 4; jj++) upk2(av[2 * jj], av[2 * jj + 1], acc2[ii][jj]);
#pragma unroll
            for (int j = 0; j < 8; j++) {
                int n = n0 + ((j < 4) ? tx * 4 + j : 64 + tx * 4 + (j - 4));
                g_XP[(size_t)m * NH + n] = av[j];
            }
        }
        return;
    }

    // ---------------- tin scan ----------------
    {
        int n = (bid - 232) * 256 + tid;
        if (n < B * NI) {
            int b = n / NI, i = n - b * NI;
            float tv = 0.f;
            for (int t = 0; t < T; t++) {
                tv = TAUc * tv + x[(b * T + t) * NI + i];
                g_TIN[((size_t)t * B + b) * NI + i] = tv;
            }
        }
    }
}

// ============================================================================
// k_fwd: 64 blocks x 384 threads.
//   threads 0..255: neuron threads, 2 neurons each (float2 gather, 8 warps)
//   warps 8..11: output LIF (5 outputs each), one step behind
// Per-neuron sums ascend row index (zero-pads bit-neutral) -> bitwise-identical
// spike trajectory. Fused reverse kappa filter + A epilogue.
// ============================================================================
__global__ __launch_bounds__(384) void k_fwd(const float* __restrict__ wrec,
                                             const float* __restrict__ wout,
                                             const float* __restrict__ label,
                                             float* __restrict__ out) {
    extern __shared__ float sm[];
    float* ws   = sm;                       // NO*NH
    float* zsh  = ws + NO * NH;             // NH
    float* errh = zsh + NH;                 // T*NO (err, then EF in place)
    int*   list = (int*)(errh + T * NO);    // NH+64
    unsigned* zmask = (unsigned*)(list + NH + 64);   // 16

    int b = blockIdx.x;
    int tid = threadIdx.x;
    int lane = tid & 31, w = tid >> 5;
    bool is_n = (tid < 256);
    int q = tid;                 // neuron thread id: owns neurons 2q, 2q+1
    int ow = w - 8;              // 0..3 for out warps

    for (int i = tid; i < NO * NH; i += 384) ws[i] = wout[i];
    for (int i = tid; i < NH; i += 384) zsh[i] = 0.f;
    __syncthreads();

    const float2* wrec2 = (const float2*)wrec;
    float hmx = 0.f, hmy = 0.f, trx = 0.f, tryy = 0.f, zsx = 0.f, zsy = 0.f;
    float om[5] = {}, os[5] = {};
    int nact = 0;

    auto do_out = [&](int tp) {
#pragma unroll
        for (int qq = 0; qq < 5; qq++) {
            int o = ow * 5 + qq;
            float s = 0.f;
#pragma unroll
            for (int c = 0; c < 16; c++)
                s += zsh[c * 32 + lane] * ws[o * NH + c * 32 + lane];
#pragma unroll
            for (int off = 16; off; off >>= 1) s += __shfl_xor_sync(0xffffffffu, s, off);
            om[qq] = TAUc * om[qq] * (1.f - os[qq]) + s;
            os[qq] = (om[qq] >= THRc) ? 1.f : 0.f;
            if (lane == 0) {
                out[((size_t)b * T + tp) * NO + o] = os[qq];
                errh[tp * NO + o] = os[qq] - label[((size_t)b * T + tp) * NO + o];
            }
        }
    };

    for (int t = 0; t < T; t++) {
        float zx = 0.f, zy = 0.f;
        unsigned nib = 0;
        if (is_n) {
            float2 xp = __ldg((const float2*)&g_XP[((size_t)t * B + b) * NH] + q);
            // dual-window float2 gather, 16 rows/window, ascending row order
            unsigned long long acc2 = 0ull;
            if (nact > 0) {
                float2 v0[16], v1[16];
                auto ldwin = [&](int base, float2* v) {
#pragma unroll
                    for (int u = 0; u < 16; u++) {
                        int ix = base + u;
                        float2 zz = {0.f, 0.f};
                        v[u] = (ix < nact) ? __ldg(&wrec2[(size_t)list[ix] * 256 + q]) : zz;
                    }
                };
                auto sumwin = [&](const float2* v) {
#pragma unroll
                    for (int u = 0; u < 16; u++) fadd2(acc2, pk2(v[u].x, v[u].y));
                };
                int npair = (nact + 31) >> 5;
                ldwin(0, v0);
                for (int pp = 0; pp < npair; pp++) {
                    ldwin(pp * 32 + 16, v1);
                    sumwin(v0);
                    ldwin(pp * 32 + 32, v0);
                    sumwin(v1);
                }
            }
            float ax, ay;
            upk2(ax, ay, acc2);

            hmx = TAUc * hmx * (1.f - zsx) + xp.x + ax;
            hmy = TAUc * hmy * (1.f - zsy) + xp.y + ay;
            zx = (hmx >= THRc) ? 1.f : 0.f;
            zy = (hmy >= THRc) ? 1.f : 0.f;
            float htx = TAUc * fmaxf(0.f, 1.f - fabsf((hmx - THRc) * (1.f / THRc)));
            float hty = TAUc * fmaxf(0.f, 1.f - fabsf((hmy - THRc) * (1.f / THRc)));
            trx  = TAUc * trx  + zsx;
            tryy = TAUc * tryy + zsy;
            size_t o2 = ((size_t)t * B + b) * 256 + q;
            float2 zv = {zx, zy}, hv = {htx, hty}, tv = {trx, tryy};
            ((float2*)g_Z)[o2] = zv; ((float2*)g_HT)[o2] = hv; ((float2*)g_TREC)[o2] = tv;
            zsx = zx; zsy = zy;

            nib = (zx != 0.f ? 1u : 0u) | (zy != 0.f ? 2u : 0u);
            // 64 bits per warp: word = warp*2 + (lane>=16); fold within 16-lane halves
            unsigned word = nib << ((lane & 15) * 2);
            word |= __shfl_xor_sync(0xffffffffu, word, 1);
            word |= __shfl_xor_sync(0xffffffffu, word, 2);
            word |= __shfl_xor_sync(0xffffffffu, word, 4);
            word |= __shfl_xor_sync(0xffffffffu, word, 8);
            if ((lane & 15) == 0) zmask[w * 2 + (lane >> 4)] = word;
        } else if (t > 0) {
            do_out(t - 1);          // reads zsh = z_{t-1}
        }
        __syncthreads();            // zsh consumers + gather done; zmask ready

        if (is_n) {
            *(float2*)&zsh[2 * q] = make_float2(zx, zy);
            int tot = 0, pre = 0;
            int myc = q >> 4;       // word covering neuron 2q
#pragma unroll
            for (int c = 0; c < 16; c++) {
                int pc = __popc(zmask[c]);
                if (c < myc) pre += pc;
                tot += pc;
            }
            pre += __popc(zmask[myc] & ((1u << ((q & 15) * 2)) - 1u));
            nact = tot;
            if (nib & 1u) list[pre++] = 2 * q;
            if (nib & 2u) list[pre++] = 2 * q + 1;
        }
        __syncthreads();            // zsh/list ready for next step
    }
    if (!is_n) do_out(T - 1);
    __syncthreads();

    // reverse kappa filter (EF in errh + g_EF)
    if (tid < NO) {
        float ef = 0.f;
        for (int t = T - 1; t >= 0; t--) {
            ef = errh[t * NO + tid] + KAPc * ef;
            errh[t * NO + tid] = ef;
            g_EF[((size_t)t * B + b) * NO + tid] = ef;
        }
    }
    __syncthreads();

    // fused A: A[t*B+b, r] = (EF[t,:] . wout[:,r]) * HT[t*B+b, r]
    for (int e = tid; e < T * NH; e += 384) {
        int t = e >> 9, r = e & (NH - 1);
        const float* ef = errh + t * NO;
        float L = 0.f;
#pragma unroll
        for (int o = 0; o < NO; o++) L += ef[o] * ws[o * NH + r];
        size_t m = (size_t)t * B + b;
        g_A[m * NH + r] = L * g_HT[m * NH + r];
    }
}

// ---------------- gemm bodies (device) ----------------
__device__ __forceinline__ void gemm128_body(
    const float* __restrict__ A, int sA,
    const float* __restrict__ Bm, int sB,
    float* __restrict__ C, int N,
    int m0, int n0, int kts, int kte,
    float* __restrict__ As, float* __restrict__ Bs)
{
    int tid = threadIdx.x, tx = tid & 15, ty = tid >> 4;
    unsigned long long acc2[8][4];
#pragma unroll
    for (int ii = 0; ii < 8; ii++)
#pragma unroll
        for (int jj = 0; jj < 4; jj++) acc2[ii][jj] = 0ull;
    float4 va[2], vb[2];

    auto ldtile = [&](int kt) {
        int k0 = kt * 16;
#pragma unroll
        for (int rep = 0; rep < 2; rep++) {
            int f = tid + rep * 256;
            int kk = f >> 5, c4 = (f & 31) * 4;
            va[rep] = *(const float4*)&A[(size_t)(k0 + kk) * sA + m0 + c4];
            int n = n0 + c4;
            const float* bp = &Bm[(size_t)(k0 + kk) * sB + n];
            float4 bv;
            if (n + 3 < N) bv = *(const float4*)bp;
            else {
                bv.x = (n + 0 < N) ? bp[0] : 0.f;
                bv.y = (n + 1 < N) ? bp[1] : 0.f;
                bv.z = (n + 2 < N) ? bp[2] : 0.f;
                bv.w = (n + 3 < N) ? bp[3] : 0.f;
            }
            vb[rep] = bv;
        }
    };
    auto sttile = [&]() {
#pragma unroll
        for (int rep = 0; rep < 2; rep++) {
            int f = tid + rep * 256;
            int kk = f >> 5, c4 = (f & 31) * 4;
            *(float4*)&As[kk * 128 + c4] = va[rep];
            *(float4*)&Bs[kk * 128 + c4] = vb[rep];
        }
    };

    ldtile(kts);
    for (int kt = kts; kt < kte; kt++) {
        sttile();
        __syncthreads();
        if (kt + 1 < kte) ldtile(kt + 1);
#pragma unroll
        for (int k = 0; k < 16; k++) {
            float a[8], bb[8];
            *(float4*)&a[0]  = *(float4*)&As[k * 128 + ty * 4];
            *(float4*)&a[4]  = *(float4*)&As[k * 128 + 64 + ty * 4];
            *(float4*)&bb[0] = *(float4*)&Bs[k * 128 + tx * 4];
            *(float4*)&bb[4] = *(float4*)&Bs[k * 128 + 64 + tx * 4];
            unsigned long long b2[4];
#pragma unroll
            for (int jj = 0; jj < 4; jj++) b2[jj] = pk2(bb[2 * jj], bb[2 * jj + 1]);
#pragma unroll
            for (int ii = 0; ii < 8; ii++) {
                unsigned long long a2 = pk2(a[ii], a[ii]);
#pragma unroll
                for (int jj = 0; jj < 4; jj++) ffma2(acc2[ii][jj], a2, b2[jj]);
            }
        }
        __syncthreads();
    }
#pragma unroll
    for (int ii = 0; ii < 8; ii++) {
        int m = m0 + ((ii < 4) ? ty * 4 + ii : 64 + ty * 4 + (ii - 4));
        float av[8];
#pragma unroll
        for (int jj = 0; jj < 4; jj++) upk2(av[2 * jj], av[2 * jj + 1], acc2[ii][jj]);
#pragma unroll
        for (int j = 0; j < 8; j++) {
            int n = n0 + ((j < 4) ? tx * 4 + j : 64 + tx * 4 + (j - 4));
            if (n < N) C[(size_t)m * N + n] = av[j];
        }
    }
}

__device__ __forceinline__ void gemm64_body(
    const float* __restrict__ A, int sA,
    const float* __restrict__ Bm, int sB,
    float* __restrict__ C, int M, int N,
    int m0, int n0, int k0s, int k0e,
    float* __restrict__ As, float* __restrict__ Bs)
{
    int tid = threadIdx.x, tx = tid & 15, ty = tid >> 4;
    float acc[4][4] = {};
    for (int k0 = k0s; k0 < k0e; k0 += 16) {
#pragma unroll
        for (int rep = 0; rep < 4; rep++) {
            int e = tid + rep * 256;
            int mm = e & 63, kk = e >> 6;
            int mg = m0 + mm;
            As[kk * 64 + mm] = (mg < M) ? A[(size_t)(k0 + kk) * sA + mg] : 0.f;
            int ng = n0 + mm;
            Bs[kk * 64 + mm] = (ng < N) ? Bm[(size_t)(k0 + kk) * sB + ng] : 0.f;
        }
        __syncthreads();
#pragma unroll
        for (int k = 0; k < 16; k++) {
            float a[4], bb[4];
#pragma unroll
            for (int i = 0; i < 4; i++) a[i]  = As[k * 64 + ty * 4 + i];
#pragma unroll
            for (int j = 0; j < 4; j++) bb[j] = Bs[k * 64 + tx * 4 + j];
#pragma unroll
            for (int i = 0; i < 4; i++)
#pragma unroll
                for (int j = 0; j < 4; j++) acc[i][j] += a[i] * bb[j];
        }
        __syncthreads();
    }
#pragma unroll
    for (int i = 0; i < 4; i++) {
        int m = m0 + ty * 4 + i;
        if (m < M) {
#pragma unroll
            for (int j = 0; j < 4; j++) {
                int n = n0 + tx * 4 + j;
                if (n < N) C[(size_t)m * N + n] = acc[i][j];
            }
        }
    }
}

// ---------------- fused gradients: gf(168) + gr(128) + go(64) = 360 blocks ----------------
__global__ __launch_bounds__(256, 2) void k_grads() {
    __shared__ float As[16 * 128];
    __shared__ float Bs[16 * 128];
    int bid = blockIdx.x;
    if (bid < 168) {
        int z = bid / 24, rem = bid - z * 24;
        int n0 = (rem % 6) * 128, m0 = (rem / 6) * 128;
        const int kst[8] = {0, 57, 114, 171, 228, 285, 342, 400};
        gemm128_body(g_A, NH, g_TIN, NI,
                     g_gp + GFP_OFF + (size_t)z * GF_MN, NI,
                     m0, n0, kst[z], kst[z + 1], As, Bs);
    } else if (bid < 296) {
        int i = bid - 168;
        int z = i / 16, rem = i - z * 16;
        int n0 = (rem % 4) * 128, m0 = (rem / 4) * 128;
        gemm128_body(g_A, NH, g_TREC, NH,
                     g_gp + GRP_OFF + (size_t)z * GR_MN, NH,
                     m0, n0, z * 50, z * 50 + 50, As, Bs);
    } else {
        int i = bid - 296;
        int z = i / 8, nx = i - z * 8;
        gemm64_body(g_EF, NO, g_Z, NH,
                    g_gp + GOP_OFF + (size_t)z * GO_MN, NO, NH,
                    0, nx * 64, z * 800, z * 800 + 800, As, Bs);
    }
}

// ---------------- fused reduce over all three gradient outputs ----------------
__global__ void k_redAll(float* __restrict__ gf, float* __restrict__ gr,
                         float* __restrict__ go) {
    int i = blockIdx.x * 256 + threadIdx.x;
    if (i < GF_MN) {
        float s = 0.f;
#pragma unroll
        for (int z = 0; z < 7; z++) s += g_gp[GFP_OFF + (size_t)z * GF_MN + i];
        gf[i] = LRc * s;
    } else if (i < GF_MN + GR_MN) {
        int j = i - GF_MN;
        float s = 0.f;
#pragma unroll
        for (int z = 0; z < 8; z++) s += g_gp[GRP_OFF + (size_t)z * GR_MN + j];
        gr[j] = LRc * s;
    } else if (i < GF_MN + GR_MN + GO_MN) {
        int j = i - GF_MN - GR_MN;
        float s = 0.f;
#pragma unroll
        for (int z = 0; z < 8; z++) s += g_gp[GOP_OFF + (size_t)z * GO_MN + j];
        go[j] = LRc * s;
    }
}

// ---------------- launch ----------------
extern "C" void kernel_launch(void* const* d_in, const int* in_sizes, int n_in,
                              void* d_out, int out_size) {
    const float* x     = (const float*)d_in[0];
    const float* label = (const float*)d_in[1];
    const float* w1    = (const float*)d_in[3];
    const float* wrec  = (const float*)d_in[4];
    const float* wout  = (const float*)d_in[5];
    float* out = (float*)d_out;
    float* gf = out + B * T * NO;          // [NH, NI]
    float* gr = gf + NH * NI;              // [NH, NH]
    float* go = gr + NH * NH;              // [NO, NH]

    cudaFuncSetAttribute(k_fwd, cudaFuncAttributeMaxDynamicSharedMemorySize, FWD_SMEM);

    k_prod<<<407, 256, PROD_SMEM>>>(x, w1);
    k_fwd<<<B, 384, FWD_SMEM>>>(wrec, wout, label, out);
    k_grads<<<360, 256>>>();
    k_redAll<<<(GF_MN + GR_MN + GO_MN + 255) / 256, 256>>>(gf, gr, go);
}